// round 14
// baseline (speedup 1.0000x reference)
#include <cuda_runtime.h>
#include <cuda_bf16.h>
#include <math.h>
#include <stdint.h>

// ---------------- problem constants ----------------
#define SZ    2048
#define NN    10
#define DD    172
#define EDGE_ 172
#define TDIM  100
#define EE    272      // D + TD
#define KDIM  444      // D + EDGE + TD
#define KDT   4440     // KDIM * N
#define HDIM  136
#define M0    (SZ*NN)  // 20480
#define NKV   544      // 272 kp | 272 vp

// output layout (floats)
#define OUT_R0 0
#define OUT_R1 3522560
#define OUT_E1 3874816
#define OUT_T1 7397376

// ---------------- scratch ----------------
__device__ float g_qp0 [M0*EE];
__device__ float g_kvp0[M0*NKV];
__device__ float g_attn0[M0*EE];
__device__ float g_a0  [M0*EE];
__device__ float g_h0  [M0*DD];
__device__ float g_qp1 [SZ*EE];
__device__ float g_kvp1[SZ*NKV];
__device__ float g_scores[2u*2048u*2048u];
__device__ float g_vT  [2*HDIM*SZ];
__device__ float g_attn1[SZ*EE];
__device__ float g_a1  [SZ*EE];
__device__ float g_h1  [SZ*DD];
__device__ float g_Wkv [NKV*KDT];   // stored as tf32 bits
__device__ float g_bkv [NKV];

static inline int cdiv(int a, int b) { return (a + b - 1) / b; }

// ---------------- tf32 helpers ----------------
__device__ __forceinline__ unsigned int f2tf32(float x)
{
    unsigned int r;
    asm("cvt.rna.tf32.f32 %0, %1;" : "=r"(r) : "f"(x));
    return r;
}
__device__ __forceinline__ float tf32r(float x)
{
    return __uint_as_float(f2tf32(x));
}

__device__ __forceinline__ void mma_tf32(float* c,
                                         unsigned int a0, unsigned int a1,
                                         unsigned int a2, unsigned int a3,
                                         unsigned int b0, unsigned int b1)
{
    asm volatile(
        "mma.sync.aligned.m16n8k8.row.col.f32.tf32.tf32.f32 "
        "{%0,%1,%2,%3}, {%4,%5,%6,%7}, {%8,%9}, {%0,%1,%2,%3};"
        : "+f"(c[0]), "+f"(c[1]), "+f"(c[2]), "+f"(c[3])
        : "r"(a0), "r"(a1), "r"(a2), "r"(a3), "r"(b0), "r"(b1));
}

// ldmatrix x4: four 8-row x 16B matrices; matches tf32 m16n8k8 fragment layout.
__device__ __forceinline__ void ldsm_x4(unsigned int* r, const void* p)
{
    unsigned int a = (unsigned int)__cvta_generic_to_shared(p);
    asm volatile("ldmatrix.sync.aligned.m8n8.x4.shared.b16 {%0,%1,%2,%3}, [%4];"
                 : "=r"(r[0]), "=r"(r[1]), "=r"(r[2]), "=r"(r[3]) : "r"(a));
}

// ---------------- A-operand gather ----------------
template<int AK>
__device__ __forceinline__ float4 loadA4(const float* __restrict__ p0,
                                         const float* __restrict__ p1,
                                         const float* __restrict__ p2,
                                         int lda, int aoff, int row, int k4)
{
    if (AK == 0) {
        return *reinterpret_cast<const float4*>(p0 + (size_t)row*lda + aoff + k4);
    } else if (AK == 1) {
        int j = k4 / KDIM;
        int c = k4 - j*KDIM;
        int nb = row*NN + j;
        const float* p;
        if (c < DD)            p = p0 + (size_t)nb*DD   + c;
        else if (c < DD+EDGE_) p = p1 + (size_t)nb*EDGE_ + (c-DD);
        else                   p = p2 + (size_t)nb*TDIM + (c-DD-EDGE_);
        return *reinterpret_cast<const float4*>(p);
    } else if (AK == 2) {
        if (k4 < DD) return *reinterpret_cast<const float4*>(p0 + (size_t)row*DD + k4);
        if (p1)      return *reinterpret_cast<const float4*>(p1 + (size_t)row*TDIM + (k4-DD));
        return make_float4(0.f,0.f,0.f,0.f);
    } else {
        if (k4 < EE) return *reinterpret_cast<const float4*>(p0 + (size_t)row*EE + k4);
        return *reinterpret_cast<const float4*>(p1 + (size_t)row*DD + (k4-EE));
    }
}

__device__ __forceinline__ uint4 cvt4(float4 v, int docvt)
{
    uint4 t;
    if (docvt) {
        t.x = f2tf32(v.x); t.y = f2tf32(v.y);
        t.z = f2tf32(v.z); t.w = f2tf32(v.w);
    } else {
        t.x = __float_as_uint(v.x); t.y = __float_as_uint(v.y);
        t.z = __float_as_uint(v.z); t.w = __float_as_uint(v.w);
    }
    return t;
}

// ================= WIDE tf32 GEMM: BM=128 BN=128 BK=16, double-buffered =======
// CVA/CVW: convert operand to tf32 at staging (0 = already tf32 bits).
template<int AK, int CVA, int CVW>
__global__ __launch_bounds__(256)
void tgemm_wide(const float* __restrict__ p0, const float* __restrict__ p1,
                const float* __restrict__ p2, int lda, int aoff,
                const float* __restrict__ W, int ldw, int woff,
                const float* __restrict__ bias,
                float* __restrict__ C, int ldc, int coff,
                int M, int N, int K, float scale, int outcv)
{
    __shared__ __align__(16) unsigned int As[2][128][20];
    __shared__ __align__(16) unsigned int Ws[2][128][20];

    const int tid  = threadIdx.x;
    const int lane = tid & 31;
    const int warp = tid >> 5;
    const int wm   = (warp & 1) * 64;
    const int wn4  = (warp >> 1) * 32;
    const int grp  = lane >> 2;
    const int qid  = lane & 3;
    const int row0 = blockIdx.y * 128;
    const int n0   = blockIdx.x * 128;

    const int a_row = lane & 15;
    const int a_col = (lane >> 4) * 4;
    const int b_row = ((lane >> 4) & 1) * 8 + (lane & 7);
    const int b_col = ((lane >> 3) & 1) * 4;

    float acc[4][4][4];
    #pragma unroll
    for (int mf = 0; mf < 4; mf++)
        #pragma unroll
        for (int nf = 0; nf < 4; nf++)
            #pragma unroll
            for (int u = 0; u < 4; u++) acc[mf][nf][u] = 0.f;

    float4 avr[2], wvr[2];
    const int r_a  = tid >> 2;
    const int kq_a = tid & 3;

    #pragma unroll
    for (int i = 0; i < 2; i++) {
        int r  = r_a + i*64;
        int ka = kq_a*4;
        avr[i] = (ka < K) ? loadA4<AK>(p0,p1,p2,lda,aoff,row0+r,ka)
                          : make_float4(0.f,0.f,0.f,0.f);
        int n  = n0 + r;
        wvr[i] = (ka < K && n < N)
            ? *reinterpret_cast<const float4*>(W + (size_t)n*ldw + woff + ka)
            : make_float4(0.f,0.f,0.f,0.f);
    }
    #pragma unroll
    for (int i = 0; i < 2; i++) {
        int r = r_a + i*64;
        *reinterpret_cast<uint4*>(&As[0][r][kq_a*4]) = cvt4(avr[i], CVA);
        *reinterpret_cast<uint4*>(&Ws[0][r][kq_a*4]) = cvt4(wvr[i], CVW);
    }
    __syncthreads();

    int buf = 0;
    for (int kt = 0; kt < K; kt += 16) {
        const bool more = (kt + 16) < K;
        if (more) {
            #pragma unroll
            for (int i = 0; i < 2; i++) {
                int r  = r_a + i*64;
                int ka = kt + 16 + kq_a*4;
                avr[i] = (ka < K) ? loadA4<AK>(p0,p1,p2,lda,aoff,row0+r,ka)
                                  : make_float4(0.f,0.f,0.f,0.f);
                int n  = n0 + r;
                wvr[i] = (ka < K && n < N)
                    ? *reinterpret_cast<const float4*>(W + (size_t)n*ldw + woff + ka)
                    : make_float4(0.f,0.f,0.f,0.f);
            }
        }

        #pragma unroll
        for (int kf = 0; kf < 2; kf++) {
            unsigned int b[4][2];
            #pragma unroll
            for (int p = 0; p < 2; p++) {
                unsigned int m[4];
                ldsm_x4(m, &Ws[buf][wn4 + p*16 + b_row][kf*8 + b_col]);
                b[2*p  ][0] = m[0]; b[2*p  ][1] = m[1];
                b[2*p+1][0] = m[2]; b[2*p+1][1] = m[3];
            }
            #pragma unroll
            for (int mf = 0; mf < 4; mf++) {
                unsigned int a[4];
                ldsm_x4(a, &As[buf][wm + mf*16 + a_row][kf*8 + a_col]);
                #pragma unroll
                for (int nf = 0; nf < 4; nf++)
                    mma_tf32(acc[mf][nf], a[0], a[1], a[2], a[3], b[nf][0], b[nf][1]);
            }
        }

        if (more) {
            int nb = buf ^ 1;
            #pragma unroll
            for (int i = 0; i < 2; i++) {
                int r = r_a + i*64;
                *reinterpret_cast<uint4*>(&As[nb][r][kq_a*4]) = cvt4(avr[i], CVA);
                *reinterpret_cast<uint4*>(&Ws[nb][r][kq_a*4]) = cvt4(wvr[i], CVW);
            }
        }
        __syncthreads();
        buf ^= 1;
    }

    #pragma unroll
    for (int mf = 0; mf < 4; mf++) {
        #pragma unroll
        for (int nf = 0; nf < 4; nf++) {
            int col = n0 + wn4 + nf*8 + 2*qid;
            if (col >= N) continue;
            float bsum0 = bias ? bias[col]   : 0.f;
            float bsum1 = bias ? bias[col+1] : 0.f;
            #pragma unroll
            for (int half = 0; half < 2; half++) {
                int row = row0 + wm + mf*16 + grp + half*8;
                if (row >= M) continue;
                float v0 = (acc[mf][nf][half*2+0] + bsum0) * scale;
                float v1 = (acc[mf][nf][half*2+1] + bsum1) * scale;
                if (outcv) { v0 = tf32r(v0); v1 = tf32r(v1); }
                float2 o = make_float2(v0, v1);
                *reinterpret_cast<float2*>(C + (size_t)row*ldc + coff + col) = o;
            }
        }
    }
}

// ================= NARROW tf32 GEMM: BM=128 BN=64 BK=16, double-buffered ======
template<int AK>
__global__ __launch_bounds__(256)
void tgemm_k(const float* __restrict__ p0, const float* __restrict__ p1,
             const float* __restrict__ p2, int lda, int aoff,
             const float* __restrict__ W, int ldw, int woff,
             const float* __restrict__ bias,
             float* __restrict__ C, int ldc, int coff,
             int M, int N, int K, float scale, int relu, int outcv)
{
    __shared__ __align__(16) unsigned int As[2][128][20];
    __shared__ __align__(16) unsigned int Ws[2][64][20];

    const int tid  = threadIdx.x;
    const int lane = tid & 31;
    const int warp = tid >> 5;
    const int wm   = (warp & 1) * 64;
    const int wn   = (warp >> 1) * 16;
    const int grp  = lane >> 2;
    const int qid  = lane & 3;
    const int row0 = blockIdx.y * 128;
    const int n0   = blockIdx.x * 64;

    const int a_row = lane & 15;
    const int a_col = (lane >> 4) * 4;
    const int b_row = ((lane >> 4) & 1) * 8 + (lane & 7);
    const int b_col = ((lane >> 3) & 1) * 4;

    float acc[4][2][4];
    #pragma unroll
    for (int mf = 0; mf < 4; mf++)
        #pragma unroll
        for (int nf = 0; nf < 2; nf++)
            #pragma unroll
            for (int u = 0; u < 4; u++) acc[mf][nf][u] = 0.f;

    float4 avr[2], wvr;
    const int r_a  = tid >> 2;
    const int kq_a = tid & 3;
    const int r_w  = tid >> 2;

    #pragma unroll
    for (int i = 0; i < 2; i++) {
        int r  = r_a + i*64;
        int ka = kq_a*4;
        avr[i] = (ka < K) ? loadA4<AK>(p0,p1,p2,lda,aoff,row0+r,ka)
                          : make_float4(0.f,0.f,0.f,0.f);
    }
    {
        int ka = kq_a*4;
        int n  = n0 + r_w;
        wvr = (ka < K && n < N)
            ? *reinterpret_cast<const float4*>(W + (size_t)n*ldw + woff + ka)
            : make_float4(0.f,0.f,0.f,0.f);
    }
    #pragma unroll
    for (int i = 0; i < 2; i++) {
        int r = r_a + i*64;
        *reinterpret_cast<uint4*>(&As[0][r][kq_a*4]) = cvt4(avr[i], 1);
    }
    *reinterpret_cast<uint4*>(&Ws[0][r_w][kq_a*4]) = cvt4(wvr, 1);
    __syncthreads();

    int buf = 0;
    for (int kt = 0; kt < K; kt += 16) {
        const bool more = (kt + 16) < K;
        if (more) {
            #pragma unroll
            for (int i = 0; i < 2; i++) {
                int r  = r_a + i*64;
                int ka = kt + 16 + kq_a*4;
                avr[i] = (ka < K) ? loadA4<AK>(p0,p1,p2,lda,aoff,row0+r,ka)
                                  : make_float4(0.f,0.f,0.f,0.f);
            }
            int ka = kt + 16 + kq_a*4;
            int n  = n0 + r_w;
            wvr = (ka < K && n < N)
                ? *reinterpret_cast<const float4*>(W + (size_t)n*ldw + woff + ka)
                : make_float4(0.f,0.f,0.f,0.f);
        }

        #pragma unroll
        for (int kf = 0; kf < 2; kf++) {
            unsigned int b[2][2];
            {
                unsigned int m[4];
                ldsm_x4(m, &Ws[buf][wn + b_row][kf*8 + b_col]);
                b[0][0] = m[0]; b[0][1] = m[1];
                b[1][0] = m[2]; b[1][1] = m[3];
            }
            #pragma unroll
            for (int mf = 0; mf < 4; mf++) {
                unsigned int a[4];
                ldsm_x4(a, &As[buf][wm + mf*16 + a_row][kf*8 + a_col]);
                #pragma unroll
                for (int nf = 0; nf < 2; nf++)
                    mma_tf32(acc[mf][nf], a[0], a[1], a[2], a[3], b[nf][0], b[nf][1]);
            }
        }

        if (more) {
            int nb = buf ^ 1;
            #pragma unroll
            for (int i = 0; i < 2; i++) {
                int r = r_a + i*64;
                *reinterpret_cast<uint4*>(&As[nb][r][kq_a*4]) = cvt4(avr[i], 1);
            }
            *reinterpret_cast<uint4*>(&Ws[nb][r_w][kq_a*4]) = cvt4(wvr, 1);
        }
        __syncthreads();
        buf ^= 1;
    }

    #pragma unroll
    for (int mf = 0; mf < 4; mf++) {
        #pragma unroll
        for (int nf = 0; nf < 2; nf++) {
            int col = n0 + wn + nf*8 + 2*qid;
            if (col >= N) continue;
            float bsum0 = bias ? bias[col]   : 0.f;
            float bsum1 = bias ? bias[col+1] : 0.f;
            #pragma unroll
            for (int half = 0; half < 2; half++) {
                int row = row0 + wm + mf*16 + grp + half*8;
                if (row >= M) continue;
                float v0 = (acc[mf][nf][half*2+0] + bsum0) * scale;
                float v1 = (acc[mf][nf][half*2+1] + bsum1) * scale;
                if (relu) { v0 = fmaxf(v0, 0.f); v1 = fmaxf(v1, 0.f); }
                if (outcv) { v0 = tf32r(v0); v1 = tf32r(v1); }
                float2 o = make_float2(v0, v1);
                *reinterpret_cast<float2*>(C + (size_t)row*ldc + coff + col) = o;
            }
        }
    }
}

// ---------------- pack Wk|Wv (pre-converted to tf32 bits) and bk|bv -----------
__global__ void pack_wkv_k(const float* __restrict__ Wk, const float* __restrict__ Wv,
                           const float* __restrict__ bk, const float* __restrict__ bv)
{
    int idx = blockIdx.x*256 + threadIdx.x;
    const int tot = NKV*KDT;
    if (idx < tot) {
        float w = (idx < EE*KDT) ? Wk[idx] : Wv[idx - EE*KDT];
        g_Wkv[idx] = tf32r(w);
    }
    if (idx < NKV)
        g_bkv[idx] = (idx < EE) ? bk[idx] : bv[idx - EE];
}

// ---------------- propagation-0 attention: per-source 10x10, H=2 ----------------
__global__ __launch_bounds__(256)
void attn0_k(const float* __restrict__ qp, const float* __restrict__ kvp,
             float* __restrict__ out)
{
    __shared__ __align__(16) float sq [NN*EE];
    __shared__ __align__(16) float skv[NN*NKV];
    __shared__ float sc[2][NN][NN];

    int s = blockIdx.x;
    int tid = threadIdx.x;
    int warp = tid >> 5;
    int lane = tid & 31;
    size_t qb = (size_t)s*NN*EE;
    size_t kb = (size_t)s*NN*NKV;

    {
        const float4* qsrc = reinterpret_cast<const float4*>(qp + qb);
        float4*       qdst = reinterpret_cast<float4*>(sq);
        for (int i = tid; i < NN*EE/4; i += 256) qdst[i] = qsrc[i];
        const float4* ksrc = reinterpret_cast<const float4*>(kvp + kb);
        float4*       kdst = reinterpret_cast<float4*>(skv);
        for (int i = tid; i < NN*NKV/4; i += 256) kdst[i] = ksrc[i];
    }
    __syncthreads();

    for (int dot = warp; dot < 2*NN*NN; dot += 8) {
        int h = dot / (NN*NN);
        int r = dot - h*NN*NN;
        int i = r / NN, j = r - i*NN;
        const float* q = sq  + i*EE  + h*HDIM;
        const float* k = skv + j*NKV + h*HDIM;
        float sum = 0.f;
        #pragma unroll
        for (int t = 0; t < 4; t++) {
            int d = lane + t*32;
            sum = fmaf(q[d], k[d], sum);
        }
        if (lane < 8) {
            int d = lane + 128;
            sum = fmaf(q[d], k[d], sum);
        }
        #pragma unroll
        for (int o = 16; o; o >>= 1) sum += __shfl_xor_sync(0xffffffffu, sum, o);
        if (lane == 0) sc[h][i][j] = sum;
    }
    __syncthreads();

    if (tid < 2*NN) {
        int h = tid / NN, i = tid - h*NN;
        float m = -1e30f;
        #pragma unroll
        for (int j = 0; j < NN; j++) m = fmaxf(m, sc[h][i][j]);
        float ssum = 0.f;
        #pragma unroll
        for (int j = 0; j < NN; j++) {
            float e = expf(sc[h][i][j] - m);
            sc[h][i][j] = e;
            ssum += e;
        }
        float inv = 1.f / ssum;
        #pragma unroll
        for (int j = 0; j < NN; j++) sc[h][i][j] *= inv;
    }
    __syncthreads();

    for (int t = tid; t < NN*EE; t += 256) {
        int i = t / EE, col = t - i*EE;
        int h = (col >= HDIM) ? 1 : 0;
        float sum = 0.f;
        #pragma unroll
        for (int j = 0; j < NN; j++)
            sum = fmaf(sc[h][i][j], skv[j*NKV + EE + col], sum);
        out[qb + t] = sum;
    }
}

// ---------------- row softmax over 2048 (prop 1) ----------------
__global__ __launch_bounds__(256)
void softmax_k(float* __restrict__ p)
{
    __shared__ float red[8];
    size_t base = (size_t)blockIdx.x * 2048;
    int tid = threadIdx.x;

    float v[8];
    float m = -1e30f;
    #pragma unroll
    for (int u = 0; u < 8; u++) {
        v[u] = p[base + tid + u*256];
        m = fmaxf(m, v[u]);
    }
    #pragma unroll
    for (int o = 16; o; o >>= 1) m = fmaxf(m, __shfl_xor_sync(0xffffffffu, m, o));
    if ((tid & 31) == 0) red[tid >> 5] = m;
    __syncthreads();
    float mm = red[0];
    #pragma unroll
    for (int i = 1; i < 8; i++) mm = fmaxf(mm, red[i]);

    float s = 0.f;
    #pragma unroll
    for (int u = 0; u < 8; u++) {
        v[u] = __expf(v[u] - mm);
        s += v[u];
    }
    #pragma unroll
    for (int o = 16; o; o >>= 1) s += __shfl_xor_sync(0xffffffffu, s, o);
    __syncthreads();
    if ((tid & 31) == 0) red[tid >> 5] = s;
    __syncthreads();
    float tot = 0.f;
    #pragma unroll
    for (int i = 0; i < 8; i++) tot += red[i];
    float inv = 1.f / tot;
    #pragma unroll
    for (int u = 0; u < 8; u++) p[base + tid + u*256] = v[u] * inv;
}

// ---------------- transpose vp1 into [h*136+d][2048] ----------------
__global__ void transpose_v_k(const float* __restrict__ kvp, float* __restrict__ vT)
{
    int idx = blockIdx.x*256 + threadIdx.x;
    if (idx >= 2*HDIM*SZ) return;
    int j  = idx & 2047;
    int hd = idx >> 11;
    vT[idx] = kvp[(size_t)j*NKV + EE + hd];
}

// ---------------- launcher ----------------
extern "C" void kernel_launch(void* const* d_in, const int* in_sizes, int n_in,
                              void* d_out, int out_size)
{
    const float* emb0  = (const float*)d_in[0];
    const float* edge0 = (const float*)d_in[1];
    const float* td0   = (const float*)d_in[2];
    const float* emb1  = (const float*)d_in[3];
    const float* edge1 = (const float*)d_in[4];
    const float* td1   = (const float*)d_in[5];
    const float* emb2  = (const float*)d_in[6];
    const float* Wq = (const float*)d_in[7];
    const float* bq = (const float*)d_in[8];
    const float* Wk = (const float*)d_in[9];
    const float* bk = (const float*)d_in[10];
    const float* Wv = (const float*)d_in[11];
    const float* bv = (const float*)d_in[12];
    const float* Wo = (const float*)d_in[13];
    const float* bo = (const float*)d_in[14];
    const float* W1 = (const float*)d_in[15];
    const float* b1 = (const float*)d_in[16];
    const float* W2 = (const float*)d_in[17];
    const float* b2 = (const float*)d_in[18];
    float* out = (float*)d_out;

    float *qp0, *kvp0, *attn0, *a0, *h0;
    float *qp1, *kvp1, *scores, *vT, *attn1, *a1, *h1, *wkv, *bkv;
    cudaGetSymbolAddress((void**)&qp0,   g_qp0);
    cudaGetSymbolAddress((void**)&kvp0,  g_kvp0);
    cudaGetSymbolAddress((void**)&attn0, g_attn0);
    cudaGetSymbolAddress((void**)&a0,    g_a0);
    cudaGetSymbolAddress((void**)&h0,    g_h0);
    cudaGetSymbolAddress((void**)&qp1,   g_qp1);
    cudaGetSymbolAddress((void**)&kvp1,  g_kvp1);
    cudaGetSymbolAddress((void**)&scores,g_scores);
    cudaGetSymbolAddress((void**)&vT,    g_vT);
    cudaGetSymbolAddress((void**)&attn1, g_attn1);
    cudaGetSymbolAddress((void**)&a1,    g_a1);
    cudaGetSymbolAddress((void**)&h1,    g_h1);
    cudaGetSymbolAddress((void**)&wkv,   g_Wkv);
    cudaGetSymbolAddress((void**)&bkv,   g_bkv);

    const float SCALE = 0.08574929257125441f;  // 1/sqrt(136)

    // ---- streams: s2 = prop-1 chain, s3 = kvp0 32-col remainder ----
    cudaStream_t s2, s3;
    cudaStreamCreate(&s2);
    cudaStreamCreate(&s3);
    cudaEvent_t eFork, eJoin, eKv;
    cudaEventCreateWithFlags(&eFork, cudaEventDisableTiming);
    cudaEventCreateWithFlags(&eJoin, cudaEventDisableTiming);
    cudaEventCreateWithFlags(&eKv,   cudaEventDisableTiming);

    pack_wkv_k<<<cdiv(NKV*KDT, 256), 256>>>(Wk, Wv, bk, bv);
    cudaEventRecord(eFork, 0);
    cudaStreamWaitEvent(s2, eFork, 0);
    cudaStreamWaitEvent(s3, eFork, 0);

    // ======== propagation 0 (default stream) ========
    tgemm_k<2><<<dim3(cdiv(EE,64), cdiv(M0,128)), 256>>>(
        emb1, td1, nullptr, 0, 0, Wq, EE, 0, bq, qp0, EE, 0, M0, EE, EE, SCALE, 0, 0);

    // kvp0 split: wide kernel covers cols 0-511 with zero tile waste;
    // narrow kernel computes cols 512-543 concurrently on s3.
    tgemm_wide<1,1,0><<<dim3(4, cdiv(M0,128)), 256>>>(
        emb0, edge0, td0, 0, 0, wkv, KDT, 0, bkv, kvp0, NKV, 0, M0, 512, KDT, 1.f, 0);
    tgemm_k<1><<<dim3(1, cdiv(M0,128)), 256, 0, s3>>>(
        emb0, edge0, td0, 0, 0, wkv + (size_t)512*KDT, KDT, 0, bkv + 512,
        kvp0, NKV, 512, M0, 32, KDT, 1.f, 0, 0);
    cudaEventRecord(eKv, s3);
    cudaStreamWaitEvent(0, eKv, 0);

    attn0_k<<<SZ, 256>>>(qp0, kvp0, attn0);
    tgemm_k<0><<<dim3(cdiv(EE,64), cdiv(M0,128)), 256>>>(
        attn0, nullptr, nullptr, EE, 0, Wo, EE, 0, bo, a0, EE, 0, M0, EE, EE, 1.f, 0, 0);
    tgemm_k<3><<<dim3(cdiv(DD,64), cdiv(M0,128)), 256>>>(
        a0, emb1, nullptr, 0, 0, W1, KDIM, 0, b1, h0, DD, 0, M0, DD, KDIM, 1.f, 1, 0);
    tgemm_k<0><<<dim3(cdiv(DD,64), cdiv(M0,128)), 256>>>(
        h0, nullptr, nullptr, DD, 0, W2, DD, 0, b2, out + OUT_R0, DD, 0, M0, DD, DD, 1.f, 0, 0);

    // ======== propagation 1 (side stream s2) ========
    tgemm_k<2><<<dim3(cdiv(EE,64), cdiv(SZ,128)), 256, 0, s2>>>(
        emb2, nullptr, nullptr, 0, 0, Wq, EE, 0, bq, qp1, EE, 0, SZ, EE, EE, SCALE, 0, 1);
    tgemm_wide<1,1,0><<<dim3(cdiv(NKV,128), cdiv(SZ,128)), 256, 0, s2>>>(
        emb1, edge1, td1, 0, 0, wkv, KDT, 0, bkv, kvp1, NKV, 0, SZ, NKV, KDT, 1.f, 1);
    for (int h = 0; h < 2; h++) {
        tgemm_wide<0,0,0><<<dim3(cdiv(SZ,128), cdiv(SZ,128)), 256, 0, s2>>>(
            qp1, nullptr, nullptr, EE, h*HDIM, kvp1, NKV, h*HDIM, nullptr,
            scores + (size_t)h*SZ*SZ, SZ, 0, SZ, SZ, HDIM, 1.f, 0);
    }
    softmax_k<<<2*SZ, 256, 0, s2>>>(scores);
    transpose_v_k<<<cdiv(2*HDIM*SZ, 256), 256, 0, s2>>>(kvp1, vT);
    for (int h = 0; h < 2; h++) {
        tgemm_k<0><<<dim3(cdiv(HDIM,64), cdiv(SZ,128)), 256, 0, s2>>>(
            scores + (size_t)h*SZ*SZ, nullptr, nullptr, SZ, 0,
            vT + (size_t)h*HDIM*SZ, SZ, 0, nullptr,
            attn1, EE, h*HDIM, SZ, HDIM, SZ, 1.f, 0, 0);
    }
    tgemm_k<0><<<dim3(cdiv(EE,64), cdiv(SZ,128)), 256, 0, s2>>>(
        attn1, nullptr, nullptr, EE, 0, Wo, EE, 0, bo, a1, EE, 0, SZ, EE, EE, 1.f, 0, 0);
    tgemm_k<3><<<dim3(cdiv(DD,64), cdiv(SZ,128)), 256, 0, s2>>>(
        a1, emb2, nullptr, 0, 0, W1, KDIM, 0, b1, h1, DD, 0, SZ, DD, KDIM, 1.f, 1, 0);
    tgemm_k<0><<<dim3(cdiv(DD,64), cdiv(SZ,128)), 256, 0, s2>>>(
        h1, nullptr, nullptr, DD, 0, W2, DD, 0, b2, out + OUT_R1, DD, 0, SZ, DD, DD, 1.f, 0, 0);

    // pass-through outputs (independent; ride on s2)
    cudaMemcpyAsync(out + OUT_E1, edge1, (size_t)SZ*NN*EDGE_*sizeof(float),
                    cudaMemcpyDeviceToDevice, s2);
    cudaMemcpyAsync(out + OUT_T1, td1, (size_t)SZ*NN*TDIM*sizeof(float),
                    cudaMemcpyDeviceToDevice, s2);

    // ---- join ----
    cudaEventRecord(eJoin, s2);
    cudaStreamWaitEvent(0, eJoin, 0);

    cudaEventDestroy(eFork);
    cudaEventDestroy(eJoin);
    cudaEventDestroy(eKv);
    cudaStreamDestroy(s2);
    cudaStreamDestroy(s3);
}

// round 15
// speedup vs baseline: 1.1115x; 1.1115x over previous
#include <cuda_runtime.h>
#include <cuda_bf16.h>
#include <math.h>
#include <stdint.h>

// ---------------- problem constants ----------------
#define SZ    2048
#define NN    10
#define DD    172
#define EDGE_ 172
#define TDIM  100
#define EE    272      // D + TD
#define KDIM  444      // D + EDGE + TD
#define KDT   4440     // KDIM * N
#define HDIM  136
#define M0    (SZ*NN)  // 20480
#define NKV   544      // 272 kp | 272 vp

// output layout (floats)
#define OUT_R0 0
#define OUT_R1 3522560
#define OUT_E1 3874816
#define OUT_T1 7397376

// ---------------- scratch ----------------
__device__ float g_qp0 [M0*EE];
__device__ float g_kvp0[M0*NKV];
__device__ float g_attn0[M0*EE];
__device__ float g_a0  [M0*EE];
__device__ float g_h0  [M0*DD];
__device__ float g_qp1 [SZ*EE];
__device__ float g_kvp1[SZ*NKV];
__device__ float g_scores[2u*2048u*2048u];
__device__ float g_vT  [2*HDIM*SZ];
__device__ float g_attn1[SZ*EE];
__device__ float g_a1  [SZ*EE];
__device__ float g_h1  [SZ*DD];
__device__ float g_Wkv [NKV*KDT];   // stored as tf32 bits
__device__ float g_bkv [NKV];

static inline int cdiv(int a, int b) { return (a + b - 1) / b; }

// ---------------- tf32 helpers ----------------
__device__ __forceinline__ unsigned int f2tf32(float x)
{
    unsigned int r;
    asm("cvt.rna.tf32.f32 %0, %1;" : "=r"(r) : "f"(x));
    return r;
}
__device__ __forceinline__ float tf32r(float x)
{
    return __uint_as_float(f2tf32(x));
}

__device__ __forceinline__ void mma_tf32(float* c,
                                         unsigned int a0, unsigned int a1,
                                         unsigned int a2, unsigned int a3,
                                         unsigned int b0, unsigned int b1)
{
    asm volatile(
        "mma.sync.aligned.m16n8k8.row.col.f32.tf32.tf32.f32 "
        "{%0,%1,%2,%3}, {%4,%5,%6,%7}, {%8,%9}, {%0,%1,%2,%3};"
        : "+f"(c[0]), "+f"(c[1]), "+f"(c[2]), "+f"(c[3])
        : "r"(a0), "r"(a1), "r"(a2), "r"(a3), "r"(b0), "r"(b1));
}

// ldmatrix x4: four 8-row x 16B matrices; matches tf32 m16n8k8 fragment layout.
__device__ __forceinline__ void ldsm_x4(unsigned int* r, const void* p)
{
    unsigned int a = (unsigned int)__cvta_generic_to_shared(p);
    asm volatile("ldmatrix.sync.aligned.m8n8.x4.shared.b16 {%0,%1,%2,%3}, [%4];"
                 : "=r"(r[0]), "=r"(r[1]), "=r"(r[2]), "=r"(r[3]) : "r"(a));
}

// cp.async 16B with zero-fill predicate (src address must be valid; bytes
// copied = pred ? 16 : 0, remainder zero-filled).
__device__ __forceinline__ void cp_async16(void* smem_dst, const void* gsrc, int pred)
{
    unsigned int d = (unsigned int)__cvta_generic_to_shared(smem_dst);
    int sz = pred ? 16 : 0;
    asm volatile("cp.async.cg.shared.global [%0], [%1], 16, %2;"
                 :: "r"(d), "l"(gsrc), "r"(sz) : "memory");
}
__device__ __forceinline__ void cp_commit()
{
    asm volatile("cp.async.commit_group;" ::: "memory");
}
__device__ __forceinline__ void cp_wait0()
{
    asm volatile("cp.async.wait_group 0;" ::: "memory");
}

// ---------------- A-operand gather ----------------
template<int AK>
__device__ __forceinline__ float4 loadA4(const float* __restrict__ p0,
                                         const float* __restrict__ p1,
                                         const float* __restrict__ p2,
                                         int lda, int aoff, int row, int k4)
{
    if (AK == 0) {
        return *reinterpret_cast<const float4*>(p0 + (size_t)row*lda + aoff + k4);
    } else if (AK == 1) {
        int j = k4 / KDIM;
        int c = k4 - j*KDIM;
        int nb = row*NN + j;
        const float* p;
        if (c < DD)            p = p0 + (size_t)nb*DD   + c;
        else if (c < DD+EDGE_) p = p1 + (size_t)nb*EDGE_ + (c-DD);
        else                   p = p2 + (size_t)nb*TDIM + (c-DD-EDGE_);
        return *reinterpret_cast<const float4*>(p);
    } else if (AK == 2) {
        if (k4 < DD) return *reinterpret_cast<const float4*>(p0 + (size_t)row*DD + k4);
        if (p1)      return *reinterpret_cast<const float4*>(p1 + (size_t)row*TDIM + (k4-DD));
        return make_float4(0.f,0.f,0.f,0.f);
    } else {
        if (k4 < EE) return *reinterpret_cast<const float4*>(p0 + (size_t)row*EE + k4);
        return *reinterpret_cast<const float4*>(p1 + (size_t)row*DD + (k4-EE));
    }
}

__device__ __forceinline__ uint4 cvt4(float4 v, int docvt)
{
    uint4 t;
    if (docvt) {
        t.x = f2tf32(v.x); t.y = f2tf32(v.y);
        t.z = f2tf32(v.z); t.w = f2tf32(v.w);
    } else {
        t.x = __float_as_uint(v.x); t.y = __float_as_uint(v.y);
        t.z = __float_as_uint(v.z); t.w = __float_as_uint(v.w);
    }
    return t;
}

// ================= WIDE tf32 GEMM: BM=128 BN=128 BK=16, double-buffered =======
// A: register staging (+optional cvt). W: cp.async direct to smem (operand must
// already hold tf32-pattern bits when CVW==0; all call sites guarantee this).
template<int AK, int CVA>
__global__ __launch_bounds__(256)
void tgemm_wide(const float* __restrict__ p0, const float* __restrict__ p1,
                const float* __restrict__ p2, int lda, int aoff,
                const float* __restrict__ W, int ldw, int woff,
                const float* __restrict__ bias,
                float* __restrict__ C, int ldc, int coff,
                int M, int N, int K, float scale, int outcv)
{
    __shared__ __align__(16) unsigned int As[2][128][20];
    __shared__ __align__(16) unsigned int Ws[2][128][20];

    const int tid  = threadIdx.x;
    const int lane = tid & 31;
    const int warp = tid >> 5;
    const int wm   = (warp & 1) * 64;
    const int wn4  = (warp >> 1) * 32;
    const int grp  = lane >> 2;
    const int qid  = lane & 3;
    const int row0 = blockIdx.y * 128;
    const int n0   = blockIdx.x * 128;

    const int a_row = lane & 15;
    const int a_col = (lane >> 4) * 4;
    const int b_row = ((lane >> 4) & 1) * 8 + (lane & 7);
    const int b_col = ((lane >> 3) & 1) * 4;

    float acc[4][4][4];
    #pragma unroll
    for (int mf = 0; mf < 4; mf++)
        #pragma unroll
        for (int nf = 0; nf < 4; nf++)
            #pragma unroll
            for (int u = 0; u < 4; u++) acc[mf][nf][u] = 0.f;

    float4 avr[2];
    const int r_a  = tid >> 2;
    const int kq_a = tid & 3;

    // W cp.async source helper (clamped address stays in-bounds; pred gates copy)
    auto w_issue = [&](int bufsel, int kbase) {
        #pragma unroll
        for (int i = 0; i < 2; i++) {
            int r  = r_a + i*64;
            int ka = kbase + kq_a*4;
            int n  = n0 + r;
            int ok = (ka < K) && (n < N);
            int kc = ok ? ka : 0;
            int nc = (n < N) ? n : (N - 1);
            const float* src = W + (size_t)nc*ldw + woff + kc;
            cp_async16(&Ws[bufsel][r][kq_a*4], src, ok);
        }
    };

    // ---- prologue ----
    #pragma unroll
    for (int i = 0; i < 2; i++) {
        int r  = r_a + i*64;
        int ka = kq_a*4;
        avr[i] = (ka < K) ? loadA4<AK>(p0,p1,p2,lda,aoff,row0+r,ka)
                          : make_float4(0.f,0.f,0.f,0.f);
    }
    w_issue(0, 0);
    cp_commit();
    #pragma unroll
    for (int i = 0; i < 2; i++) {
        int r = r_a + i*64;
        *reinterpret_cast<uint4*>(&As[0][r][kq_a*4]) = cvt4(avr[i], CVA);
    }
    cp_wait0();
    __syncthreads();

    int buf = 0;
    for (int kt = 0; kt < K; kt += 16) {
        const bool more = (kt + 16) < K;
        if (more) {
            #pragma unroll
            for (int i = 0; i < 2; i++) {
                int r  = r_a + i*64;
                int ka = kt + 16 + kq_a*4;
                avr[i] = (ka < K) ? loadA4<AK>(p0,p1,p2,lda,aoff,row0+r,ka)
                                  : make_float4(0.f,0.f,0.f,0.f);
            }
            w_issue(buf ^ 1, kt + 16);
            cp_commit();
        }

        #pragma unroll
        for (int kf = 0; kf < 2; kf++) {
            unsigned int b[4][2];
            #pragma unroll
            for (int p = 0; p < 2; p++) {
                unsigned int m[4];
                ldsm_x4(m, &Ws[buf][wn4 + p*16 + b_row][kf*8 + b_col]);
                b[2*p  ][0] = m[0]; b[2*p  ][1] = m[1];
                b[2*p+1][0] = m[2]; b[2*p+1][1] = m[3];
            }
            #pragma unroll
            for (int mf = 0; mf < 4; mf++) {
                unsigned int a[4];
                ldsm_x4(a, &As[buf][wm + mf*16 + a_row][kf*8 + a_col]);
                #pragma unroll
                for (int nf = 0; nf < 4; nf++)
                    mma_tf32(acc[mf][nf], a[0], a[1], a[2], a[3], b[nf][0], b[nf][1]);
            }
        }

        if (more) {
            int nb = buf ^ 1;
            #pragma unroll
            for (int i = 0; i < 2; i++) {
                int r = r_a + i*64;
                *reinterpret_cast<uint4*>(&As[nb][r][kq_a*4]) = cvt4(avr[i], CVA);
            }
            cp_wait0();
        }
        __syncthreads();
        buf ^= 1;
    }

    #pragma unroll
    for (int mf = 0; mf < 4; mf++) {
        #pragma unroll
        for (int nf = 0; nf < 4; nf++) {
            int col = n0 + wn4 + nf*8 + 2*qid;
            if (col >= N) continue;
            float bsum0 = bias ? bias[col]   : 0.f;
            float bsum1 = bias ? bias[col+1] : 0.f;
            #pragma unroll
            for (int half = 0; half < 2; half++) {
                int row = row0 + wm + mf*16 + grp + half*8;
                if (row >= M) continue;
                float v0 = (acc[mf][nf][half*2+0] + bsum0) * scale;
                float v1 = (acc[mf][nf][half*2+1] + bsum1) * scale;
                if (outcv) { v0 = tf32r(v0); v1 = tf32r(v1); }
                float2 o = make_float2(v0, v1);
                *reinterpret_cast<float2*>(C + (size_t)row*ldc + coff + col) = o;
            }
        }
    }
}

// ================= NARROW tf32 GEMM: BM=128 BN=64 BK=16, double-buffered ======
template<int AK>
__global__ __launch_bounds__(256)
void tgemm_k(const float* __restrict__ p0, const float* __restrict__ p1,
             const float* __restrict__ p2, int lda, int aoff,
             const float* __restrict__ W, int ldw, int woff,
             const float* __restrict__ bias,
             float* __restrict__ C, int ldc, int coff,
             int M, int N, int K, float scale, int relu, int outcv)
{
    __shared__ __align__(16) unsigned int As[2][128][20];
    __shared__ __align__(16) unsigned int Ws[2][64][20];

    const int tid  = threadIdx.x;
    const int lane = tid & 31;
    const int warp = tid >> 5;
    const int wm   = (warp & 1) * 64;
    const int wn   = (warp >> 1) * 16;
    const int grp  = lane >> 2;
    const int qid  = lane & 3;
    const int row0 = blockIdx.y * 128;
    const int n0   = blockIdx.x * 64;

    const int a_row = lane & 15;
    const int a_col = (lane >> 4) * 4;
    const int b_row = ((lane >> 4) & 1) * 8 + (lane & 7);
    const int b_col = ((lane >> 3) & 1) * 4;

    float acc[4][2][4];
    #pragma unroll
    for (int mf = 0; mf < 4; mf++)
        #pragma unroll
        for (int nf = 0; nf < 2; nf++)
            #pragma unroll
            for (int u = 0; u < 4; u++) acc[mf][nf][u] = 0.f;

    float4 avr[2], wvr;
    const int r_a  = tid >> 2;
    const int kq_a = tid & 3;
    const int r_w  = tid >> 2;

    #pragma unroll
    for (int i = 0; i < 2; i++) {
        int r  = r_a + i*64;
        int ka = kq_a*4;
        avr[i] = (ka < K) ? loadA4<AK>(p0,p1,p2,lda,aoff,row0+r,ka)
                          : make_float4(0.f,0.f,0.f,0.f);
    }
    {
        int ka = kq_a*4;
        int n  = n0 + r_w;
        wvr = (ka < K && n < N)
            ? *reinterpret_cast<const float4*>(W + (size_t)n*ldw + woff + ka)
            : make_float4(0.f,0.f,0.f,0.f);
    }
    #pragma unroll
    for (int i = 0; i < 2; i++) {
        int r = r_a + i*64;
        *reinterpret_cast<uint4*>(&As[0][r][kq_a*4]) = cvt4(avr[i], 1);
    }
    *reinterpret_cast<uint4*>(&Ws[0][r_w][kq_a*4]) = cvt4(wvr, 1);
    __syncthreads();

    int buf = 0;
    for (int kt = 0; kt < K; kt += 16) {
        const bool more = (kt + 16) < K;
        if (more) {
            #pragma unroll
            for (int i = 0; i < 2; i++) {
                int r  = r_a + i*64;
                int ka = kt + 16 + kq_a*4;
                avr[i] = (ka < K) ? loadA4<AK>(p0,p1,p2,lda,aoff,row0+r,ka)
                                  : make_float4(0.f,0.f,0.f,0.f);
            }
            int ka = kt + 16 + kq_a*4;
            int n  = n0 + r_w;
            wvr = (ka < K && n < N)
                ? *reinterpret_cast<const float4*>(W + (size_t)n*ldw + woff + ka)
                : make_float4(0.f,0.f,0.f,0.f);
        }

        #pragma unroll
        for (int kf = 0; kf < 2; kf++) {
            unsigned int b[2][2];
            {
                unsigned int m[4];
                ldsm_x4(m, &Ws[buf][wn + b_row][kf*8 + b_col]);
                b[0][0] = m[0]; b[0][1] = m[1];
                b[1][0] = m[2]; b[1][1] = m[3];
            }
            #pragma unroll
            for (int mf = 0; mf < 4; mf++) {
                unsigned int a[4];
                ldsm_x4(a, &As[buf][wm + mf*16 + a_row][kf*8 + a_col]);
                #pragma unroll
                for (int nf = 0; nf < 2; nf++)
                    mma_tf32(acc[mf][nf], a[0], a[1], a[2], a[3], b[nf][0], b[nf][1]);
            }
        }

        if (more) {
            int nb = buf ^ 1;
            #pragma unroll
            for (int i = 0; i < 2; i++) {
                int r = r_a + i*64;
                *reinterpret_cast<uint4*>(&As[nb][r][kq_a*4]) = cvt4(avr[i], 1);
            }
            *reinterpret_cast<uint4*>(&Ws[nb][r_w][kq_a*4]) = cvt4(wvr, 1);
        }
        __syncthreads();
        buf ^= 1;
    }

    #pragma unroll
    for (int mf = 0; mf < 4; mf++) {
        #pragma unroll
        for (int nf = 0; nf < 2; nf++) {
            int col = n0 + wn + nf*8 + 2*qid;
            if (col >= N) continue;
            float bsum0 = bias ? bias[col]   : 0.f;
            float bsum1 = bias ? bias[col+1] : 0.f;
            #pragma unroll
            for (int half = 0; half < 2; half++) {
                int row = row0 + wm + mf*16 + grp + half*8;
                if (row >= M) continue;
                float v0 = (acc[mf][nf][half*2+0] + bsum0) * scale;
                float v1 = (acc[mf][nf][half*2+1] + bsum1) * scale;
                if (relu) { v0 = fmaxf(v0, 0.f); v1 = fmaxf(v1, 0.f); }
                if (outcv) { v0 = tf32r(v0); v1 = tf32r(v1); }
                float2 o = make_float2(v0, v1);
                *reinterpret_cast<float2*>(C + (size_t)row*ldc + coff + col) = o;
            }
        }
    }
}

// ---------------- pack Wk|Wv (pre-converted to tf32 bits) and bk|bv -----------
__global__ void pack_wkv_k(const float* __restrict__ Wk, const float* __restrict__ Wv,
                           const float* __restrict__ bk, const float* __restrict__ bv)
{
    int idx = blockIdx.x*256 + threadIdx.x;
    const int tot = NKV*KDT;
    if (idx < tot) {
        float w = (idx < EE*KDT) ? Wk[idx] : Wv[idx - EE*KDT];
        g_Wkv[idx] = tf32r(w);
    }
    if (idx < NKV)
        g_bkv[idx] = (idx < EE) ? bk[idx] : bv[idx - EE];
}

// ---------------- propagation-0 attention: per-source 10x10, H=2 ----------------
__global__ __launch_bounds__(256)
void attn0_k(const float* __restrict__ qp, const float* __restrict__ kvp,
             float* __restrict__ out)
{
    __shared__ __align__(16) float sq [NN*EE];
    __shared__ __align__(16) float skv[NN*NKV];
    __shared__ float sc[2][NN][NN];

    int s = blockIdx.x;
    int tid = threadIdx.x;
    int warp = tid >> 5;
    int lane = tid & 31;
    size_t qb = (size_t)s*NN*EE;
    size_t kb = (size_t)s*NN*NKV;

    {
        const float4* qsrc = reinterpret_cast<const float4*>(qp + qb);
        float4*       qdst = reinterpret_cast<float4*>(sq);
        for (int i = tid; i < NN*EE/4; i += 256) qdst[i] = qsrc[i];
        const float4* ksrc = reinterpret_cast<const float4*>(kvp + kb);
        float4*       kdst = reinterpret_cast<float4*>(skv);
        for (int i = tid; i < NN*NKV/4; i += 256) kdst[i] = ksrc[i];
    }
    __syncthreads();

    for (int dot = warp; dot < 2*NN*NN; dot += 8) {
        int h = dot / (NN*NN);
        int r = dot - h*NN*NN;
        int i = r / NN, j = r - i*NN;
        const float* q = sq  + i*EE  + h*HDIM;
        const float* k = skv + j*NKV + h*HDIM;
        float sum = 0.f;
        #pragma unroll
        for (int t = 0; t < 4; t++) {
            int d = lane + t*32;
            sum = fmaf(q[d], k[d], sum);
        }
        if (lane < 8) {
            int d = lane + 128;
            sum = fmaf(q[d], k[d], sum);
        }
        #pragma unroll
        for (int o = 16; o; o >>= 1) sum += __shfl_xor_sync(0xffffffffu, sum, o);
        if (lane == 0) sc[h][i][j] = sum;
    }
    __syncthreads();

    if (tid < 2*NN) {
        int h = tid / NN, i = tid - h*NN;
        float m = -1e30f;
        #pragma unroll
        for (int j = 0; j < NN; j++) m = fmaxf(m, sc[h][i][j]);
        float ssum = 0.f;
        #pragma unroll
        for (int j = 0; j < NN; j++) {
            float e = expf(sc[h][i][j] - m);
            sc[h][i][j] = e;
            ssum += e;
        }
        float inv = 1.f / ssum;
        #pragma unroll
        for (int j = 0; j < NN; j++) sc[h][i][j] *= inv;
    }
    __syncthreads();

    for (int t = tid; t < NN*EE; t += 256) {
        int i = t / EE, col = t - i*EE;
        int h = (col >= HDIM) ? 1 : 0;
        float sum = 0.f;
        #pragma unroll
        for (int j = 0; j < NN; j++)
            sum = fmaf(sc[h][i][j], skv[j*NKV + EE + col], sum);
        out[qb + t] = sum;
    }
}

// ---------------- row softmax over 2048 (prop 1) ----------------
__global__ __launch_bounds__(256)
void softmax_k(float* __restrict__ p)
{
    __shared__ float red[8];
    size_t base = (size_t)blockIdx.x * 2048;
    int tid = threadIdx.x;

    float v[8];
    float m = -1e30f;
    #pragma unroll
    for (int u = 0; u < 8; u++) {
        v[u] = p[base + tid + u*256];
        m = fmaxf(m, v[u]);
    }
    #pragma unroll
    for (int o = 16; o; o >>= 1) m = fmaxf(m, __shfl_xor_sync(0xffffffffu, m, o));
    if ((tid & 31) == 0) red[tid >> 5] = m;
    __syncthreads();
    float mm = red[0];
    #pragma unroll
    for (int i = 1; i < 8; i++) mm = fmaxf(mm, red[i]);

    float s = 0.f;
    #pragma unroll
    for (int u = 0; u < 8; u++) {
        v[u] = __expf(v[u] - mm);
        s += v[u];
    }
    #pragma unroll
    for (int o = 16; o; o >>= 1) s += __shfl_xor_sync(0xffffffffu, s, o);
    __syncthreads();
    if ((tid & 31) == 0) red[tid >> 5] = s;
    __syncthreads();
    float tot = 0.f;
    #pragma unroll
    for (int i = 0; i < 8; i++) tot += red[i];
    float inv = 1.f / tot;
    #pragma unroll
    for (int u = 0; u < 8; u++) p[base + tid + u*256] = v[u] * inv;
}

// ---------------- transpose vp1 into [h*136+d][2048] ----------------
__global__ void transpose_v_k(const float* __restrict__ kvp, float* __restrict__ vT)
{
    int idx = blockIdx.x*256 + threadIdx.x;
    if (idx >= 2*HDIM*SZ) return;
    int j  = idx & 2047;
    int hd = idx >> 11;
    vT[idx] = kvp[(size_t)j*NKV + EE + hd];
}

// ---------------- launcher ----------------
extern "C" void kernel_launch(void* const* d_in, const int* in_sizes, int n_in,
                              void* d_out, int out_size)
{
    const float* emb0  = (const float*)d_in[0];
    const float* edge0 = (const float*)d_in[1];
    const float* td0   = (const float*)d_in[2];
    const float* emb1  = (const float*)d_in[3];
    const float* edge1 = (const float*)d_in[4];
    const float* td1   = (const float*)d_in[5];
    const float* emb2  = (const float*)d_in[6];
    const float* Wq = (const float*)d_in[7];
    const float* bq = (const float*)d_in[8];
    const float* Wk = (const float*)d_in[9];
    const float* bk = (const float*)d_in[10];
    const float* Wv = (const float*)d_in[11];
    const float* bv = (const float*)d_in[12];
    const float* Wo = (const float*)d_in[13];
    const float* bo = (const float*)d_in[14];
    const float* W1 = (const float*)d_in[15];
    const float* b1 = (const float*)d_in[16];
    const float* W2 = (const float*)d_in[17];
    const float* b2 = (const float*)d_in[18];
    float* out = (float*)d_out;

    float *qp0, *kvp0, *attn0, *a0, *h0;
    float *qp1, *kvp1, *scores, *vT, *attn1, *a1, *h1, *wkv, *bkv;
    cudaGetSymbolAddress((void**)&qp0,   g_qp0);
    cudaGetSymbolAddress((void**)&kvp0,  g_kvp0);
    cudaGetSymbolAddress((void**)&attn0, g_attn0);
    cudaGetSymbolAddress((void**)&a0,    g_a0);
    cudaGetSymbolAddress((void**)&h0,    g_h0);
    cudaGetSymbolAddress((void**)&qp1,   g_qp1);
    cudaGetSymbolAddress((void**)&kvp1,  g_kvp1);
    cudaGetSymbolAddress((void**)&scores,g_scores);
    cudaGetSymbolAddress((void**)&vT,    g_vT);
    cudaGetSymbolAddress((void**)&attn1, g_attn1);
    cudaGetSymbolAddress((void**)&a1,    g_a1);
    cudaGetSymbolAddress((void**)&h1,    g_h1);
    cudaGetSymbolAddress((void**)&wkv,   g_Wkv);
    cudaGetSymbolAddress((void**)&bkv,   g_bkv);

    const float SCALE = 0.08574929257125441f;  // 1/sqrt(136)

    // ---- fork/join: prop-1 chain is fully independent of prop-0 ----
    cudaStream_t s2;
    cudaStreamCreate(&s2);
    cudaEvent_t eFork, eJoin;
    cudaEventCreateWithFlags(&eFork, cudaEventDisableTiming);
    cudaEventCreateWithFlags(&eJoin, cudaEventDisableTiming);

    pack_wkv_k<<<cdiv(NKV*KDT, 256), 256>>>(Wk, Wv, bk, bv);
    cudaEventRecord(eFork, 0);
    cudaStreamWaitEvent(s2, eFork, 0);

    // ======== propagation 0 (default stream) ========
    tgemm_k<2><<<dim3(cdiv(EE,64), cdiv(M0,128)), 256>>>(
        emb1, td1, nullptr, 0, 0, Wq, EE, 0, bq, qp0, EE, 0, M0, EE, EE, SCALE, 0, 0);
    tgemm_wide<1,1><<<dim3(cdiv(NKV,128), cdiv(M0,128)), 256>>>(
        emb0, edge0, td0, 0, 0, wkv, KDT, 0, bkv, kvp0, NKV, 0, M0, NKV, KDT, 1.f, 0);
    attn0_k<<<SZ, 256>>>(qp0, kvp0, attn0);
    tgemm_k<0><<<dim3(cdiv(EE,64), cdiv(M0,128)), 256>>>(
        attn0, nullptr, nullptr, EE, 0, Wo, EE, 0, bo, a0, EE, 0, M0, EE, EE, 1.f, 0, 0);
    tgemm_k<3><<<dim3(cdiv(DD,64), cdiv(M0,128)), 256>>>(
        a0, emb1, nullptr, 0, 0, W1, KDIM, 0, b1, h0, DD, 0, M0, DD, KDIM, 1.f, 1, 0);
    tgemm_k<0><<<dim3(cdiv(DD,64), cdiv(M0,128)), 256>>>(
        h0, nullptr, nullptr, DD, 0, W2, DD, 0, b2, out + OUT_R0, DD, 0, M0, DD, DD, 1.f, 0, 0);

    // ======== propagation 1 (side stream s2) ========
    tgemm_k<2><<<dim3(cdiv(EE,64), cdiv(SZ,128)), 256, 0, s2>>>(
        emb2, nullptr, nullptr, 0, 0, Wq, EE, 0, bq, qp1, EE, 0, SZ, EE, EE, SCALE, 0, 1);
    tgemm_wide<1,1><<<dim3(cdiv(NKV,128), cdiv(SZ,128)), 256, 0, s2>>>(
        emb1, edge1, td1, 0, 0, wkv, KDT, 0, bkv, kvp1, NKV, 0, SZ, NKV, KDT, 1.f, 1);
    for (int h = 0; h < 2; h++) {
        // qp1 (A) and kvp1 (W) both carry tf32-pattern bits -> CVA=0, cp.async W ok
        tgemm_wide<0,0><<<dim3(cdiv(SZ,128), cdiv(SZ,128)), 256, 0, s2>>>(
            qp1, nullptr, nullptr, EE, h*HDIM, kvp1, NKV, h*HDIM, nullptr,
            scores + (size_t)h*SZ*SZ, SZ, 0, SZ, SZ, HDIM, 1.f, 0);
    }
    softmax_k<<<2*SZ, 256, 0, s2>>>(scores);
    transpose_v_k<<<cdiv(2*HDIM*SZ, 256), 256, 0, s2>>>(kvp1, vT);
    for (int h = 0; h < 2; h++) {
        tgemm_k<0><<<dim3(cdiv(HDIM,64), cdiv(SZ,128)), 256, 0, s2>>>(
            scores + (size_t)h*SZ*SZ, nullptr, nullptr, SZ, 0,
            vT + (size_t)h*HDIM*SZ, SZ, 0, nullptr,
            attn1, EE, h*HDIM, SZ, HDIM, SZ, 1.f, 0, 0);
    }
    tgemm_k<0><<<dim3(cdiv(EE,64), cdiv(SZ,128)), 256, 0, s2>>>(
        attn1, nullptr, nullptr, EE, 0, Wo, EE, 0, bo, a1, EE, 0, SZ, EE, EE, 1.f, 0, 0);
    tgemm_k<3><<<dim3(cdiv(DD,64), cdiv(SZ,128)), 256, 0, s2>>>(
        a1, emb2, nullptr, 0, 0, W1, KDIM, 0, b1, h1, DD, 0, SZ, DD, KDIM, 1.f, 1, 0);
    tgemm_k<0><<<dim3(cdiv(DD,64), cdiv(SZ,128)), 256, 0, s2>>>(
        h1, nullptr, nullptr, DD, 0, W2, DD, 0, b2, out + OUT_R1, DD, 0, SZ, DD, DD, 1.f, 0, 0);

    // pass-through outputs (independent; ride on s2)
    cudaMemcpyAsync(out + OUT_E1, edge1, (size_t)SZ*NN*EDGE_*sizeof(float),
                    cudaMemcpyDeviceToDevice, s2);
    cudaMemcpyAsync(out + OUT_T1, td1, (size_t)SZ*NN*TDIM*sizeof(float),
                    cudaMemcpyDeviceToDevice, s2);

    // ---- join ----
    cudaEventRecord(eJoin, s2);
    cudaStreamWaitEvent(0, eJoin, 0);

    cudaEventDestroy(eFork);
    cudaEventDestroy(eJoin);
    cudaStreamDestroy(s2);
}